// round 7
// baseline (speedup 1.0000x reference)
#include <cuda_runtime.h>

#define NF   128
#define NSEG 4096
#define MAXN 100000
#define MAXE 1000000

typedef unsigned long long u64;

// ---- scratch (device globals: no runtime allocation allowed) ----
__device__ float    g_Pj[MAXN * NF];
__device__ float    g_Pi[MAXN * NF];    // holds Pi + bias (bias folded in epilogue)
__device__ float    g_alpha[MAXE];
__device__ unsigned g_segmax[NSEG];
__device__ float    g_segsum[NSEG];

// monotone float<->uint encoding so atomicMax works on signed floats
__device__ __forceinline__ unsigned fenc(float f) {
    unsigned b = __float_as_uint(f);
    return (b & 0x80000000u) ? ~b : (b | 0x80000000u);
}
__device__ __forceinline__ float fdec(unsigned u) {
    return __uint_as_float((u & 0x80000000u) ? (u & 0x7FFFFFFFu) : ~u);
}

// packed fp32x2 helpers (FFMA2 — only reachable via PTX on sm_103a)
__device__ __forceinline__ u64 pack2(float x) {
    u64 r; asm("mov.b64 %0, {%1, %1};" : "=l"(r) : "f"(x)); return r;
}
__device__ __forceinline__ u64 ffma2(u64 a, u64 b, u64 c) {
    u64 d; asm("fma.rn.f32x2 %0, %1, %2, %3;" : "=l"(d) : "l"(a), "l"(b), "l"(c));
    return d;
}
__device__ __forceinline__ float2 unpack2(u64 v) {
    float2 r; asm("mov.b64 {%0, %1}, %2;" : "=f"(r.x), "=f"(r.y) : "l"(v));
    return r;
}

__global__ void init_kernel() {
    int i = blockIdx.x * blockDim.x + threadIdx.x;
    if (i < NSEG) { g_segmax[i] = 0u; g_segsum[i] = 0.0f; }
}

// ---------------------------------------------------------------------------
// Projection GEMM: P[n, c] = sum_k X[n, k] * W[k, c],  K = N = 128.
// blockIdx.y selects (x_j,w_j)->g_Pj or (x_i,w_i)->g_Pi (+bias fold).
// 256 threads -> 128x128 tile, 8 rows x 4 f32x2-column-pairs per thread.
// Inner loop uses fma.rn.f32x2 (FFMA2): 32 packed FMAs/thread/k instead of
// 64 scalar FFMA -> 2x fp32 throughput; W read as ulonglong2 (2 LDS.128/k).
// ---------------------------------------------------------------------------
__global__ __launch_bounds__(256)
void proj_kernel(const float* __restrict__ Xj, const float* __restrict__ Wj,
                 const float* __restrict__ Xi, const float* __restrict__ Wi,
                 const float* __restrict__ bias, int nrows) {
    const bool addb = (blockIdx.y == 1);
    const float* __restrict__ X = addb ? Xi : Xj;
    const float* __restrict__ W = addb ? Wi : Wj;
    float* __restrict__ P = addb ? g_Pi : g_Pj;

    __shared__ __align__(16) float xsT[32 * 129];   // [k][row], padded
    __shared__ __align__(16) float ws [32 * NF];    // [k][c]

    const int tid = threadIdx.x;
    const int tx  = tid & 15;
    const int ty  = tid >> 4;
    const int rowBase = blockIdx.x * 128;

    // acc2[i][p]: row ty*8+i, column pairs {tx*4,tx*4+1},{tx*4+2,tx*4+3},
    //                                       {64+tx*4,...},{64+tx*4+2,...}
    u64 acc2[8][4];
#pragma unroll
    for (int i = 0; i < 8; i++)
#pragma unroll
        for (int j = 0; j < 4; j++) acc2[i][j] = 0ull;   // = (+0.0f, +0.0f)

    const ulonglong2* wsu2 = reinterpret_cast<const ulonglong2*>(ws);

    for (int kk = 0; kk < NF; kk += 32) {
#pragma unroll
        for (int p = 0; p < 4; p++) {
            int idx = p * 256 + tid;
            int row = idx >> 3;
            int kq  = idx & 7;
            int gr  = rowBase + row;
            float4 v = make_float4(0.f, 0.f, 0.f, 0.f);
            if (gr < nrows)
                v = *reinterpret_cast<const float4*>(X + gr * NF + kk + kq * 4);
            xsT[(kq * 4 + 0) * 129 + row] = v.x;
            xsT[(kq * 4 + 1) * 129 + row] = v.y;
            xsT[(kq * 4 + 2) * 129 + row] = v.z;
            xsT[(kq * 4 + 3) * 129 + row] = v.w;
        }
#pragma unroll
        for (int p = 0; p < 4; p++) {
            int idx = p * 256 + tid;
            int k  = idx >> 5;
            int cq = idx & 31;
            *reinterpret_cast<float4*>(ws + k * NF + cq * 4) =
                *reinterpret_cast<const float4*>(W + (kk + k) * NF + cq * 4);
        }
        __syncthreads();

#pragma unroll
        for (int k = 0; k < 32; k++) {
            float xv[8];
#pragma unroll
            for (int i = 0; i < 8; i++) xv[i] = xsT[k * 129 + ty * 8 + i];
            // W pairs: (c0,c1),(c2,c3) for c=tx*4 and c=64+tx*4
            ulonglong2 wA = wsu2[k * 32 + tx];        // cols tx*4 .. +3
            ulonglong2 wB = wsu2[k * 32 + 16 + tx];   // cols 64+tx*4 .. +3
#pragma unroll
            for (int i = 0; i < 8; i++) {
                u64 xp = pack2(xv[i]);
                acc2[i][0] = ffma2(xp, wA.x, acc2[i][0]);
                acc2[i][1] = ffma2(xp, wA.y, acc2[i][1]);
                acc2[i][2] = ffma2(xp, wB.x, acc2[i][2]);
                acc2[i][3] = ffma2(xp, wB.y, acc2[i][3]);
            }
        }
        __syncthreads();
    }

    float4 bv0 = make_float4(0.f, 0.f, 0.f, 0.f), bv1 = bv0;
    if (addb) {
        bv0 = *reinterpret_cast<const float4*>(bias + tx * 4);
        bv1 = *reinterpret_cast<const float4*>(bias + 64 + tx * 4);
    }
#pragma unroll
    for (int i = 0; i < 8; i++) {
        int gr = rowBase + ty * 8 + i;
        if (gr < nrows) {
            float2 p0 = unpack2(acc2[i][0]);
            float2 p1 = unpack2(acc2[i][1]);
            float2 p2 = unpack2(acc2[i][2]);
            float2 p3 = unpack2(acc2[i][3]);
            *reinterpret_cast<float4*>(P + gr * NF + tx * 4) =
                make_float4(p0.x + bv0.x, p0.y + bv0.y, p1.x + bv0.z, p1.y + bv0.w);
            *reinterpret_cast<float4*>(P + gr * NF + 64 + tx * 4) =
                make_float4(p2.x + bv1.x, p2.y + bv1.y, p3.x + bv1.z, p3.y + bv1.w);
        }
    }
}

// ---------------------------------------------------------------------------
// alpha[e] = PReLU(Pj[src] + Pi'[dst]) . mlpW + mlpb   (bias already in Pi')
// R2 layout (empirically fastest): ONE warp per edge, lane owns feature
// lane*4, MLP_p1=2 (stays under the L1tex-queue contention knee).
// Fused segmented max: lane 0 does one fire-and-forget atomicMax per edge
// (1M REDGs over 4096 addresses — negligible), removing the segmax pass.
// ---------------------------------------------------------------------------
__global__ __launch_bounds__(256)
void edge_alpha_kernel(const int* __restrict__ ei,
                       const int* __restrict__ seg,
                       const float* __restrict__ prelu_w,
                       const float* __restrict__ mlpW,
                       const float* __restrict__ mlpb, int E) {
    const int e    = (blockIdx.x * blockDim.x + threadIdx.x) >> 5;
    const int lane = threadIdx.x & 31;
    if (e >= E) return;

    const float4 w  = reinterpret_cast<const float4*>(mlpW)[lane];
    const float  pw = prelu_w[0];
    const float  mb = mlpb[0];

    const int src = ei[e];          // uniform across warp -> broadcast wf
    const int dst = ei[E + e];
    const int sg  = seg[e];

    const float4 a = reinterpret_cast<const float4*>(g_Pj)[(size_t)src * 32 + lane];
    const float4 b = reinterpret_cast<const float4*>(g_Pi)[(size_t)dst * 32 + lane];

    float h, s;
    h = a.x + b.x; h = (h >= 0.f) ? h : pw * h; s  = h * w.x;
    h = a.y + b.y; h = (h >= 0.f) ? h : pw * h; s += h * w.y;
    h = a.z + b.z; h = (h >= 0.f) ? h : pw * h; s += h * w.z;
    h = a.w + b.w; h = (h >= 0.f) ? h : pw * h; s += h * w.w;

#pragma unroll
    for (int o = 16; o > 0; o >>= 1)
        s += __shfl_xor_sync(0xffffffffu, s, o);

    if (lane == 0) {
        const float alpha = s + mb;
        g_alpha[e] = alpha;
        atomicMax(&g_segmax[sg], fenc(alpha));   // fused segmented max
    }
}

// e = exp(alpha - segmax); store to out; warp-segmented suffix-sum + atomicAdd
__global__ __launch_bounds__(256)
void expsum_kernel(const int* __restrict__ seg, float* __restrict__ out, int E) {
    int i    = blockIdx.x * blockDim.x + threadIdx.x;
    int lane = threadIdx.x & 31;
    float e = 0.0f;
    int   s = -1;
    if (i < E) {
        s = seg[i];
        float m = fdec(g_segmax[s]);
        e = __expf(g_alpha[i] - m);
        out[i] = e;
    }
    float sum = e;
#pragma unroll
    for (int o = 1; o < 32; o <<= 1) {
        float av = __shfl_down_sync(0xffffffffu, sum, o);
        int   sv = __shfl_down_sync(0xffffffffu, s, o);
        if (lane + o < 32 && sv == s) sum += av;
    }
    int sp = __shfl_up_sync(0xffffffffu, s, 1);
    bool head = (lane == 0) || (sp != s);
    if (i < E && head) atomicAdd(&g_segsum[s], sum);
}

__global__ __launch_bounds__(256)
void norm_kernel(const int* __restrict__ seg, float* __restrict__ out, int E) {
    int i = blockIdx.x * blockDim.x + threadIdx.x;
    if (i < E) out[i] = out[i] / (g_segsum[seg[i]] + 1e-16f);
}

// ---------------------------------------------------------------------------
extern "C" void kernel_launch(void* const* d_in, const int* in_sizes, int n_in,
                              void* d_out, int out_size) {
    const float* x_j   = (const float*)d_in[0];
    const float* x_i   = (const float*)d_in[1];
    const int*   ei    = (const int*)  d_in[2];
    const int*   seg   = (const int*)  d_in[3];
    const float* w_j   = (const float*)d_in[4];
    const float* w_i   = (const float*)d_in[5];
    const float* bias  = (const float*)d_in[6];
    const float* prelu = (const float*)d_in[7];
    const float* mlpW  = (const float*)d_in[8];
    const float* mlpb  = (const float*)d_in[9];

    int nnodes = in_sizes[0] / NF;
    int E      = in_sizes[3];
    float* out = (float*)d_out;

    init_kernel<<<(NSEG + 255) / 256, 256>>>();

    dim3 pg((nnodes + 127) / 128, 2);
    proj_kernel<<<pg, 256>>>(x_j, w_j, x_i, w_i, bias, nnodes);

    // one warp per edge (R2 layout)
    long long nthreads = (long long)E * 32;
    edge_alpha_kernel<<<(unsigned)((nthreads + 255) / 256), 256>>>(
        ei, seg, prelu, mlpW, mlpb, E);

    int eb = (E + 255) / 256;
    expsum_kernel<<<eb, 256>>>(seg, out, E);
    norm_kernel  <<<eb, 256>>>(seg, out, E);
}

// round 8
// speedup vs baseline: 1.2526x; 1.2526x over previous
#include <cuda_runtime.h>

#define NF   128
#define NSEG 4096
#define MAXN 100000
#define MAXE 1000000

// ---- scratch (device globals: no runtime allocation allowed) ----
__device__ float    g_Pj[MAXN * NF];
__device__ float    g_Pi[MAXN * NF];    // holds Pi + bias (bias folded in epilogue)
__device__ float    g_alpha[MAXE];
__device__ unsigned g_segmax[NSEG];
__device__ float    g_segsum[NSEG];

// monotone float<->uint encoding so atomicMax works on signed floats
__device__ __forceinline__ unsigned fenc(float f) {
    unsigned b = __float_as_uint(f);
    return (b & 0x80000000u) ? ~b : (b | 0x80000000u);
}
__device__ __forceinline__ float fdec(unsigned u) {
    return __uint_as_float((u & 0x80000000u) ? (u & 0x7FFFFFFFu) : ~u);
}

__global__ void init_kernel() {
    int i = blockIdx.x * blockDim.x + threadIdx.x;
    if (i < NSEG) { g_segmax[i] = 0u; g_segsum[i] = 0.0f; }
}

// ---------------------------------------------------------------------------
// Projection GEMM (exact R2 scalar version — measured 150 us, FFMA roofline).
// P[n, c] = sum_k X[n, k] * W[k, c],  K = N = 128.
// blockIdx.y selects (x_j,w_j)->g_Pj or (x_i,w_i)->g_Pi (+bias fold).
// 256 threads -> 128x128 tile, 8x8 thread tile.
// ---------------------------------------------------------------------------
__global__ __launch_bounds__(256)
void proj_kernel(const float* __restrict__ Xj, const float* __restrict__ Wj,
                 const float* __restrict__ Xi, const float* __restrict__ Wi,
                 const float* __restrict__ bias, int nrows) {
    const bool addb = (blockIdx.y == 1);
    const float* __restrict__ X = addb ? Xi : Xj;
    const float* __restrict__ W = addb ? Wi : Wj;
    float* __restrict__ P = addb ? g_Pi : g_Pj;

    __shared__ float xsT[32 * 129];   // [k][row], padded
    __shared__ float ws [32 * NF];    // [k][c]

    const int tid = threadIdx.x;
    const int tx  = tid & 15;
    const int ty  = tid >> 4;
    const int rowBase = blockIdx.x * 128;

    float acc[8][8];
#pragma unroll
    for (int i = 0; i < 8; i++)
#pragma unroll
        for (int j = 0; j < 8; j++) acc[i][j] = 0.0f;

    for (int kk = 0; kk < NF; kk += 32) {
#pragma unroll
        for (int p = 0; p < 4; p++) {
            int idx = p * 256 + tid;
            int row = idx >> 3;
            int kq  = idx & 7;
            int gr  = rowBase + row;
            float4 v = make_float4(0.f, 0.f, 0.f, 0.f);
            if (gr < nrows)
                v = *reinterpret_cast<const float4*>(X + gr * NF + kk + kq * 4);
            xsT[(kq * 4 + 0) * 129 + row] = v.x;
            xsT[(kq * 4 + 1) * 129 + row] = v.y;
            xsT[(kq * 4 + 2) * 129 + row] = v.z;
            xsT[(kq * 4 + 3) * 129 + row] = v.w;
        }
#pragma unroll
        for (int p = 0; p < 4; p++) {
            int idx = p * 256 + tid;
            int k  = idx >> 5;
            int cq = idx & 31;
            *reinterpret_cast<float4*>(ws + k * NF + cq * 4) =
                *reinterpret_cast<const float4*>(W + (kk + k) * NF + cq * 4);
        }
        __syncthreads();

#pragma unroll
        for (int k = 0; k < 32; k++) {
            float xv[8];
#pragma unroll
            for (int i = 0; i < 8; i++) xv[i] = xsT[k * 129 + ty * 8 + i];
            float4 w0 = *reinterpret_cast<const float4*>(ws + k * NF + tx * 4);
            float4 w1 = *reinterpret_cast<const float4*>(ws + k * NF + 64 + tx * 4);
#pragma unroll
            for (int i = 0; i < 8; i++) {
                acc[i][0] += xv[i] * w0.x;
                acc[i][1] += xv[i] * w0.y;
                acc[i][2] += xv[i] * w0.z;
                acc[i][3] += xv[i] * w0.w;
                acc[i][4] += xv[i] * w1.x;
                acc[i][5] += xv[i] * w1.y;
                acc[i][6] += xv[i] * w1.z;
                acc[i][7] += xv[i] * w1.w;
            }
        }
        __syncthreads();
    }

    float4 bv0 = make_float4(0.f, 0.f, 0.f, 0.f), bv1 = bv0;
    if (addb) {
        bv0 = *reinterpret_cast<const float4*>(bias + tx * 4);
        bv1 = *reinterpret_cast<const float4*>(bias + 64 + tx * 4);
    }
#pragma unroll
    for (int i = 0; i < 8; i++) {
        int gr = rowBase + ty * 8 + i;
        if (gr < nrows) {
            *reinterpret_cast<float4*>(P + gr * NF + tx * 4) =
                make_float4(acc[i][0] + bv0.x, acc[i][1] + bv0.y,
                            acc[i][2] + bv0.z, acc[i][3] + bv0.w);
            *reinterpret_cast<float4*>(P + gr * NF + 64 + tx * 4) =
                make_float4(acc[i][4] + bv1.x, acc[i][5] + bv1.y,
                            acc[i][6] + bv1.z, acc[i][7] + bv1.w);
        }
    }
}

// ---------------------------------------------------------------------------
// alpha[e] = PReLU(Pj[src] + Pi'[dst]) . mlpW + mlpb   (bias already in Pi')
// R2 layout (empirically fastest): ONE warp per edge, lane owns feature
// lane*4, MLP_p1=2 (stays under the L1tex-queue contention knee).
// Fused segmented max: lane 0 does one fire-and-forget atomicMax per edge
// (1M REDG.MAX over 4096 addresses — a few us of LTS atomic time),
// removing the separate segmax pass.
// ---------------------------------------------------------------------------
__global__ __launch_bounds__(256)
void edge_alpha_kernel(const int* __restrict__ ei,
                       const int* __restrict__ seg,
                       const float* __restrict__ prelu_w,
                       const float* __restrict__ mlpW,
                       const float* __restrict__ mlpb, int E) {
    const int e    = (blockIdx.x * blockDim.x + threadIdx.x) >> 5;
    const int lane = threadIdx.x & 31;
    if (e >= E) return;

    const float4 w  = reinterpret_cast<const float4*>(mlpW)[lane];
    const float  pw = prelu_w[0];
    const float  mb = mlpb[0];

    const int src = ei[e];          // uniform across warp -> broadcast wf
    const int dst = ei[E + e];
    const int sg  = seg[e];

    const float4 a = reinterpret_cast<const float4*>(g_Pj)[(size_t)src * 32 + lane];
    const float4 b = reinterpret_cast<const float4*>(g_Pi)[(size_t)dst * 32 + lane];

    float h, s;
    h = a.x + b.x; h = (h >= 0.f) ? h : pw * h; s  = h * w.x;
    h = a.y + b.y; h = (h >= 0.f) ? h : pw * h; s += h * w.y;
    h = a.z + b.z; h = (h >= 0.f) ? h : pw * h; s += h * w.z;
    h = a.w + b.w; h = (h >= 0.f) ? h : pw * h; s += h * w.w;

#pragma unroll
    for (int o = 16; o > 0; o >>= 1)
        s += __shfl_xor_sync(0xffffffffu, s, o);

    if (lane == 0) {
        const float alpha = s + mb;
        g_alpha[e] = alpha;
        atomicMax(&g_segmax[sg], fenc(alpha));   // fused segmented max
    }
}

// e = exp(alpha - segmax); store to out; warp-segmented suffix-sum + atomicAdd
__global__ __launch_bounds__(256)
void expsum_kernel(const int* __restrict__ seg, float* __restrict__ out, int E) {
    int i    = blockIdx.x * blockDim.x + threadIdx.x;
    int lane = threadIdx.x & 31;
    float e = 0.0f;
    int   s = -1;
    if (i < E) {
        s = seg[i];
        float m = fdec(g_segmax[s]);
        e = __expf(g_alpha[i] - m);
        out[i] = e;
    }
    float sum = e;
#pragma unroll
    for (int o = 1; o < 32; o <<= 1) {
        float av = __shfl_down_sync(0xffffffffu, sum, o);
        int   sv = __shfl_down_sync(0xffffffffu, s, o);
        if (lane + o < 32 && sv == s) sum += av;
    }
    int sp = __shfl_up_sync(0xffffffffu, s, 1);
    bool head = (lane == 0) || (sp != s);
    if (i < E && head) atomicAdd(&g_segsum[s], sum);
}

__global__ __launch_bounds__(256)
void norm_kernel(const int* __restrict__ seg, float* __restrict__ out, int E) {
    int i = blockIdx.x * blockDim.x + threadIdx.x;
    if (i < E) out[i] = out[i] / (g_segsum[seg[i]] + 1e-16f);
}

// ---------------------------------------------------------------------------
extern "C" void kernel_launch(void* const* d_in, const int* in_sizes, int n_in,
                              void* d_out, int out_size) {
    const float* x_j   = (const float*)d_in[0];
    const float* x_i   = (const float*)d_in[1];
    const int*   ei    = (const int*)  d_in[2];
    const int*   seg   = (const int*)  d_in[3];
    const float* w_j   = (const float*)d_in[4];
    const float* w_i   = (const float*)d_in[5];
    const float* bias  = (const float*)d_in[6];
    const float* prelu = (const float*)d_in[7];
    const float* mlpW  = (const float*)d_in[8];
    const float* mlpb  = (const float*)d_in[9];

    int nnodes = in_sizes[0] / NF;
    int E      = in_sizes[3];
    float* out = (float*)d_out;

    init_kernel<<<(NSEG + 255) / 256, 256>>>();

    dim3 pg((nnodes + 127) / 128, 2);
    proj_kernel<<<pg, 256>>>(x_j, w_j, x_i, w_i, bias, nnodes);

    // one warp per edge (R2 layout)
    long long nthreads = (long long)E * 32;
    edge_alpha_kernel<<<(unsigned)((nthreads + 255) / 256), 256>>>(
        ei, seg, prelu, mlpW, mlpb, E);

    int eb = (E + 255) / 256;
    expsum_kernel<<<eb, 256>>>(seg, out, E);
    norm_kernel  <<<eb, 256>>>(seg, out, E);
}

// round 9
// speedup vs baseline: 1.8934x; 1.5116x over previous
#include <cuda_runtime.h>

#define NF   128
#define NSEG 4096
#define MAXN 100000
#define MAXE 1000000

// ---- scratch (device globals: no runtime allocation allowed) ----
__device__ float    g_Pj[MAXN * NF];
__device__ float    g_Pi[MAXN * NF];    // holds Pi + bias (bias folded in epilogue)
__device__ float    g_alpha[MAXE];
__device__ unsigned g_segmax[NSEG];
__device__ float    g_segsum[NSEG];

// monotone float<->uint encoding so atomicMax works on signed floats
__device__ __forceinline__ unsigned fenc(float f) {
    unsigned b = __float_as_uint(f);
    return (b & 0x80000000u) ? ~b : (b | 0x80000000u);
}
__device__ __forceinline__ float fdec(unsigned u) {
    return __uint_as_float((u & 0x80000000u) ? (u & 0x7FFFFFFFu) : ~u);
}

__global__ void init_kernel() {
    int i = blockIdx.x * blockDim.x + threadIdx.x;
    if (i < NSEG) { g_segmax[i] = 0u; g_segsum[i] = 0.0f; }
}

// ---------------------------------------------------------------------------
// Projection GEMM (exact R2 structure: one launch per matrix, `which` arg).
// P[n, c] = sum_k X[n, k] * W[k, c],  K = N = 128.
// 256 threads -> 128x128 tile, 8x8 thread tile. FFMA-roofline (~75 us each).
// which==1 additionally folds bias into the epilogue (P = Xi@Wi + bias).
// ---------------------------------------------------------------------------
__global__ __launch_bounds__(256)
void proj_kernel(const float* __restrict__ X, const float* __restrict__ W,
                 const float* __restrict__ bias, int nrows, int which) {
    float* __restrict__ P = which ? g_Pi : g_Pj;
    __shared__ float xsT[32 * 129];   // [k][row], padded
    __shared__ float ws [32 * NF];    // [k][c]

    const int tid = threadIdx.x;
    const int tx  = tid & 15;
    const int ty  = tid >> 4;
    const int rowBase = blockIdx.x * 128;

    float acc[8][8];
#pragma unroll
    for (int i = 0; i < 8; i++)
#pragma unroll
        for (int j = 0; j < 8; j++) acc[i][j] = 0.0f;

    for (int kk = 0; kk < NF; kk += 32) {
#pragma unroll
        for (int p = 0; p < 4; p++) {
            int idx = p * 256 + tid;
            int row = idx >> 3;
            int kq  = idx & 7;
            int gr  = rowBase + row;
            float4 v = make_float4(0.f, 0.f, 0.f, 0.f);
            if (gr < nrows)
                v = *reinterpret_cast<const float4*>(X + gr * NF + kk + kq * 4);
            xsT[(kq * 4 + 0) * 129 + row] = v.x;
            xsT[(kq * 4 + 1) * 129 + row] = v.y;
            xsT[(kq * 4 + 2) * 129 + row] = v.z;
            xsT[(kq * 4 + 3) * 129 + row] = v.w;
        }
#pragma unroll
        for (int p = 0; p < 4; p++) {
            int idx = p * 256 + tid;
            int k  = idx >> 5;
            int cq = idx & 31;
            *reinterpret_cast<float4*>(ws + k * NF + cq * 4) =
                *reinterpret_cast<const float4*>(W + (kk + k) * NF + cq * 4);
        }
        __syncthreads();

#pragma unroll
        for (int k = 0; k < 32; k++) {
            float xv[8];
#pragma unroll
            for (int i = 0; i < 8; i++) xv[i] = xsT[k * 129 + ty * 8 + i];
            float4 w0 = *reinterpret_cast<const float4*>(ws + k * NF + tx * 4);
            float4 w1 = *reinterpret_cast<const float4*>(ws + k * NF + 64 + tx * 4);
#pragma unroll
            for (int i = 0; i < 8; i++) {
                acc[i][0] += xv[i] * w0.x;
                acc[i][1] += xv[i] * w0.y;
                acc[i][2] += xv[i] * w0.z;
                acc[i][3] += xv[i] * w0.w;
                acc[i][4] += xv[i] * w1.x;
                acc[i][5] += xv[i] * w1.y;
                acc[i][6] += xv[i] * w1.z;
                acc[i][7] += xv[i] * w1.w;
            }
        }
        __syncthreads();
    }

    float4 bv0 = make_float4(0.f, 0.f, 0.f, 0.f), bv1 = bv0;
    if (which) {
        bv0 = *reinterpret_cast<const float4*>(bias + tx * 4);
        bv1 = *reinterpret_cast<const float4*>(bias + 64 + tx * 4);
    }
#pragma unroll
    for (int i = 0; i < 8; i++) {
        int gr = rowBase + ty * 8 + i;
        if (gr < nrows) {
            *reinterpret_cast<float4*>(P + gr * NF + tx * 4) =
                make_float4(acc[i][0] + bv0.x, acc[i][1] + bv0.y,
                            acc[i][2] + bv0.z, acc[i][3] + bv0.w);
            *reinterpret_cast<float4*>(P + gr * NF + 64 + tx * 4) =
                make_float4(acc[i][4] + bv1.x, acc[i][5] + bv1.y,
                            acc[i][6] + bv1.z, acc[i][7] + bv1.w);
        }
    }
}

// ---------------------------------------------------------------------------
// alpha[e] = PReLU(Pj[src] + Pi'[dst]) . mlpW + mlpb   (bias already in Pi')
// R2 layout exactly (the only one that measured fast): ONE warp per edge,
// lane owns feature lane*4, MLP_p1=2. Bias load removed (folded into Pi).
// NO fused atomic — sorted seg ids make per-edge atomics serialize at LTS
// (measured +160 us in R6/R7); the warp-pre-reduced segmax pass is cheaper.
// ---------------------------------------------------------------------------
__global__ __launch_bounds__(256)
void edge_alpha_kernel(const int* __restrict__ ei,
                       const float* __restrict__ prelu_w,
                       const float* __restrict__ mlpW,
                       const float* __restrict__ mlpb, int E) {
    const int e    = (blockIdx.x * blockDim.x + threadIdx.x) >> 5;
    const int lane = threadIdx.x & 31;
    if (e >= E) return;

    const float4 w  = reinterpret_cast<const float4*>(mlpW)[lane];
    const float  pw = prelu_w[0];
    const float  mb = mlpb[0];

    const int src = ei[e];          // warp-uniform -> broadcast wavefront
    const int dst = ei[E + e];

    const float4 a = reinterpret_cast<const float4*>(g_Pj)[(size_t)src * 32 + lane];
    const float4 b = reinterpret_cast<const float4*>(g_Pi)[(size_t)dst * 32 + lane];

    float h, s;
    h = a.x + b.x; h = (h >= 0.f) ? h : pw * h; s  = h * w.x;
    h = a.y + b.y; h = (h >= 0.f) ? h : pw * h; s += h * w.y;
    h = a.z + b.z; h = (h >= 0.f) ? h : pw * h; s += h * w.z;
    h = a.w + b.w; h = (h >= 0.f) ? h : pw * h; s += h * w.w;

#pragma unroll
    for (int o = 16; o > 0; o >>= 1)
        s += __shfl_xor_sync(0xffffffffu, s, o);

    if (lane == 0) g_alpha[e] = s + mb;
}

// ---------------------------------------------------------------------------
// Segmented max over sorted segment ids: warp-segmented suffix-max, one
// atomicMax per per-warp run head (~40K atomics total -> cheap at LTS).
// ---------------------------------------------------------------------------
__global__ __launch_bounds__(256)
void segmax_kernel(const int* __restrict__ seg, int E) {
    int i    = blockIdx.x * blockDim.x + threadIdx.x;
    int lane = threadIdx.x & 31;
    float a = -3.4e38f;
    int   s = -1;
    if (i < E) { a = g_alpha[i]; s = seg[i]; }
#pragma unroll
    for (int o = 1; o < 32; o <<= 1) {
        float av = __shfl_down_sync(0xffffffffu, a, o);
        int   sv = __shfl_down_sync(0xffffffffu, s, o);
        if (lane + o < 32 && sv == s) a = fmaxf(a, av);
    }
    int sp = __shfl_up_sync(0xffffffffu, s, 1);
    bool head = (lane == 0) || (sp != s);
    if (i < E && head) atomicMax(&g_segmax[s], fenc(a));
}

// e = exp(alpha - segmax); store to out; warp-segmented suffix-sum + atomicAdd
__global__ __launch_bounds__(256)
void expsum_kernel(const int* __restrict__ seg, float* __restrict__ out, int E) {
    int i    = blockIdx.x * blockDim.x + threadIdx.x;
    int lane = threadIdx.x & 31;
    float e = 0.0f;
    int   s = -1;
    if (i < E) {
        s = seg[i];
        float m = fdec(g_segmax[s]);
        e = __expf(g_alpha[i] - m);
        out[i] = e;
    }
    float sum = e;
#pragma unroll
    for (int o = 1; o < 32; o <<= 1) {
        float av = __shfl_down_sync(0xffffffffu, sum, o);
        int   sv = __shfl_down_sync(0xffffffffu, s, o);
        if (lane + o < 32 && sv == s) sum += av;
    }
    int sp = __shfl_up_sync(0xffffffffu, s, 1);
    bool head = (lane == 0) || (sp != s);
    if (i < E && head) atomicAdd(&g_segsum[s], sum);
}

__global__ __launch_bounds__(256)
void norm_kernel(const int* __restrict__ seg, float* __restrict__ out, int E) {
    int i = blockIdx.x * blockDim.x + threadIdx.x;
    if (i < E) out[i] = out[i] / (g_segsum[seg[i]] + 1e-16f);
}

// ---------------------------------------------------------------------------
extern "C" void kernel_launch(void* const* d_in, const int* in_sizes, int n_in,
                              void* d_out, int out_size) {
    const float* x_j   = (const float*)d_in[0];
    const float* x_i   = (const float*)d_in[1];
    const int*   ei    = (const int*)  d_in[2];
    const int*   seg   = (const int*)  d_in[3];
    const float* w_j   = (const float*)d_in[4];
    const float* w_i   = (const float*)d_in[5];
    const float* bias  = (const float*)d_in[6];
    const float* prelu = (const float*)d_in[7];
    const float* mlpW  = (const float*)d_in[8];
    const float* mlpb  = (const float*)d_in[9];

    int nnodes = in_sizes[0] / NF;
    int E      = in_sizes[3];
    float* out = (float*)d_out;

    init_kernel<<<(NSEG + 255) / 256, 256>>>();

    int gblocks = (nnodes + 127) / 128;
    proj_kernel<<<gblocks, 256>>>(x_j, w_j, bias, nnodes, 0);
    proj_kernel<<<gblocks, 256>>>(x_i, w_i, bias, nnodes, 1);

    // one warp per edge (R2 layout)
    long long nthreads = (long long)E * 32;
    edge_alpha_kernel<<<(unsigned)((nthreads + 255) / 256), 256>>>(
        ei, prelu, mlpW, mlpb, E);

    int eb = (E + 255) / 256;
    segmax_kernel<<<eb, 256>>>(seg, E);
    expsum_kernel<<<eb, 256>>>(seg, out, E);
    norm_kernel  <<<eb, 256>>>(seg, out, E);
}

// round 11
// speedup vs baseline: 2.0245x; 1.0692x over previous
#include <cuda_runtime.h>
#include <cuda_bf16.h>
#include <cstdint>

#define NF   128
#define NSEG 4096
#define MAXN 100000
#define MAXE 1000000

// ---- scratch (device globals: no runtime allocation allowed) ----
__device__ float    g_Pj[MAXN * NF];
__device__ float    g_Pi[MAXN * NF];    // holds Pi + bias (bias folded in epilogue)
__device__ float    g_alpha[MAXE];
__device__ unsigned g_segmax[NSEG];
__device__ float    g_segsum[NSEG];

// monotone float<->uint encoding so atomicMax works on signed floats
__device__ __forceinline__ unsigned fenc(float f) {
    unsigned b = __float_as_uint(f);
    return (b & 0x80000000u) ? ~b : (b | 0x80000000u);
}
__device__ __forceinline__ float fdec(unsigned u) {
    return __uint_as_float((u & 0x80000000u) ? (u & 0x7FFFFFFFu) : ~u);
}

__global__ void init_kernel() {
    int i = blockIdx.x * blockDim.x + threadIdx.x;
    if (i < NSEG) { g_segmax[i] = 0u; g_segsum[i] = 0.0f; }
}

// ---------------------------------------------------------------------------
// mma.sync helpers (baseline PTX — compiles under plain compute_103,
// unlike tcgen05 which needs the sm_103a feature target)
// ---------------------------------------------------------------------------
__device__ __forceinline__ uint32_t smem_u32(const void* p) {
    uint32_t a;
    asm("{ .reg .u64 t; cvta.to.shared.u64 t, %1; cvt.u32.u64 %0, t; }"
        : "=r"(a) : "l"(p));
    return a;
}
__device__ __forceinline__ void ldm_x4(uint32_t* r, uint32_t addr) {
    asm volatile("ldmatrix.sync.aligned.m8n8.x4.shared.b16 {%0,%1,%2,%3}, [%4];"
                 : "=r"(r[0]), "=r"(r[1]), "=r"(r[2]), "=r"(r[3]) : "r"(addr));
}
__device__ __forceinline__ void ldm_x2t(uint32_t* r, uint32_t addr) {
    asm volatile("ldmatrix.sync.aligned.m8n8.x2.trans.shared.b16 {%0,%1}, [%2];"
                 : "=r"(r[0]), "=r"(r[1]) : "r"(addr));
}
__device__ __forceinline__ void mma16816(float* c, const uint32_t* a, const uint32_t* b) {
    asm volatile(
        "mma.sync.aligned.m16n8k16.row.col.f32.bf16.bf16.f32 "
        "{%0,%1,%2,%3}, {%4,%5,%6,%7}, {%8,%9}, {%0,%1,%2,%3};"
        : "+f"(c[0]), "+f"(c[1]), "+f"(c[2]), "+f"(c[3])
        : "r"(a[0]), "r"(a[1]), "r"(a[2]), "r"(a[3]), "r"(b[0]), "r"(b[1]));
}
// pack two fp32 into one u32 of 2 bf16 (hi part) and the residual (lo part)
__device__ __forceinline__ void split2(float x, float y, uint32_t& hi, uint32_t& lo) {
    __nv_bfloat16 hx = __float2bfloat16(x), hy = __float2bfloat16(y);
    __nv_bfloat16 lx = __float2bfloat16(x - __bfloat162float(hx));
    __nv_bfloat16 ly = __float2bfloat16(y - __bfloat162float(hy));
    hi = (uint32_t)__bfloat16_as_ushort(hx) | ((uint32_t)__bfloat16_as_ushort(hy) << 16);
    lo = (uint32_t)__bfloat16_as_ushort(lx) | ((uint32_t)__bfloat16_as_ushort(ly) << 16);
}

// ---------------------------------------------------------------------------
// Tensor-core projection: P[tile 128x128] = X_tile @ W (+bias if which==1)
// bf16 split-GEMM: D = Ahi*Whi + Alo*Whi + Ahi*Wlo, fp32 accumulators.
// 8 warps in 2x4; warp tile 64x32 = 4x4 m16n8k16 tiles. smem pitch 136 bf16
// (rows shift 16B -> conflict-free ldmatrix). Epilogue via smem (pitch 129).
// ---------------------------------------------------------------------------
#define TCP 136                       // smem pitch in bf16
#define PLANE (128 * TCP * 2)         // 34816 B per plane
#define SM_WH 0
#define SM_WL (PLANE)
#define SM_AH (2 * PLANE)
#define SM_AL (3 * PLANE)
#define SMEM_TC (4 * PLANE)           // 139264 B

__global__ __launch_bounds__(256)
void proj_tc_kernel(const float* __restrict__ X, const float* __restrict__ W,
                    const float* __restrict__ bias, int nrows, int which) {
    extern __shared__ char smem[];
    float* __restrict__ P = which ? g_Pi : g_Pj;
    const int tid = threadIdx.x, wid = tid >> 5, lane = tid & 31;
    const int rowBase = blockIdx.x * 128;

    // ---- stage W hi/lo planes: 4096 float4 chunks over 256 threads ----
#pragma unroll
    for (int it = 0; it < 16; ++it) {
        int f = it * 256 + tid;
        int k = f >> 5, c4 = (f & 31) * 4;
        float4 v = *reinterpret_cast<const float4*>(W + k * NF + c4);
        uint2 h, l;
        split2(v.x, v.y, h.x, l.x);
        split2(v.z, v.w, h.y, l.y);
        uint32_t off = (uint32_t)(k * TCP + c4) * 2;
        *reinterpret_cast<uint2*>(smem + SM_WH + off) = h;
        *reinterpret_cast<uint2*>(smem + SM_WL + off) = l;
    }
    // ---- stage A hi/lo planes ----
#pragma unroll
    for (int it = 0; it < 16; ++it) {
        int f = it * 256 + tid;
        int r = f >> 5, c4 = (f & 31) * 4;
        int gr = rowBase + r;
        float4 v = make_float4(0.f, 0.f, 0.f, 0.f);
        if (gr < nrows) v = *reinterpret_cast<const float4*>(X + gr * NF + c4);
        uint2 h, l;
        split2(v.x, v.y, h.x, l.x);
        split2(v.z, v.w, h.y, l.y);
        uint32_t off = (uint32_t)(r * TCP + c4) * 2;
        *reinterpret_cast<uint2*>(smem + SM_AH + off) = h;
        *reinterpret_cast<uint2*>(smem + SM_AL + off) = l;
    }
    __syncthreads();

    const int wr = wid >> 2;      // 0..1 : 64-row block
    const int wc = wid & 3;       // 0..3 : 32-col block
    const uint32_t sb = smem_u32(smem);

    float acc[4][4][4];
#pragma unroll
    for (int mt = 0; mt < 4; ++mt)
#pragma unroll
        for (int nt = 0; nt < 4; ++nt)
#pragma unroll
            for (int c = 0; c < 4; ++c) acc[mt][nt][c] = 0.0f;

    // per-lane ldmatrix address components
    const int aRow = wr * 64 + (lane & 15);          // + mt*16
    const int aCol = (lane >> 4) << 3;               // + kk
    const int bCol = wc * 32;                        // + nt*8
    const int bRowL = (lane & 15);                   // + kk

#pragma unroll
    for (int split = 0; split < 3; ++split) {
        const uint32_t aBase = sb + ((split == 1) ? SM_AL : SM_AH);
        const uint32_t bBase = sb + ((split == 2) ? SM_WL : SM_WH);
#pragma unroll
        for (int kk = 0; kk < 128; kk += 16) {
            uint32_t a[4][4], b[4][2];
#pragma unroll
            for (int mt = 0; mt < 4; ++mt)
                ldm_x4(a[mt], aBase + (uint32_t)((aRow + mt * 16) * TCP + aCol + kk) * 2);
#pragma unroll
            for (int nt = 0; nt < 4; ++nt)
                ldm_x2t(b[nt], bBase + (uint32_t)((bRowL + kk) * TCP + bCol + nt * 8) * 2);
#pragma unroll
            for (int mt = 0; mt < 4; ++mt)
#pragma unroll
                for (int nt = 0; nt < 4; ++nt)
                    mma16816(acc[mt][nt], a[mt], b[nt]);
        }
    }
    __syncthreads();   // A/W smem dead -> reuse for epilogue

    // ---- epilogue: regs -> smem (pitch 129) -> coalesced gmem (+bias) ----
    float* ds = reinterpret_cast<float*>(smem);
    const int cr = lane >> 2;          // fragment row within 8
    const int cc = (lane & 3) * 2;     // fragment col pair
#pragma unroll
    for (int mt = 0; mt < 4; ++mt)
#pragma unroll
        for (int nt = 0; nt < 4; ++nt) {
            int r0 = wr * 64 + mt * 16 + cr;
            int c0 = wc * 32 + nt * 8 + cc;
            ds[r0 * 129 + c0]           = acc[mt][nt][0];
            ds[r0 * 129 + c0 + 1]       = acc[mt][nt][1];
            ds[(r0 + 8) * 129 + c0]     = acc[mt][nt][2];
            ds[(r0 + 8) * 129 + c0 + 1] = acc[mt][nt][3];
        }
    __syncthreads();
#pragma unroll
    for (int it = 0; it < 16; ++it) {
        int f = it * 256 + tid;
        int r = f >> 5, c4 = (f & 31) * 4;
        int gr = rowBase + r;
        if (gr < nrows) {
            float4 o;
            o.x = ds[r * 129 + c4 + 0];
            o.y = ds[r * 129 + c4 + 1];
            o.z = ds[r * 129 + c4 + 2];
            o.w = ds[r * 129 + c4 + 3];
            if (which) {
                float4 bv = *reinterpret_cast<const float4*>(bias + c4);
                o.x += bv.x; o.y += bv.y; o.z += bv.z; o.w += bv.w;
            }
            *reinterpret_cast<float4*>(P + gr * NF + c4) = o;
        }
    }
}

// ---------------------------------------------------------------------------
// alpha[e] = PReLU(Pj[src] + Pi'[dst]) . mlpW + mlpb   (bias already in Pi')
// EXACT R8 version (one warp per edge — the only layout that measured fast).
// ---------------------------------------------------------------------------
__global__ __launch_bounds__(256)
void edge_alpha_kernel(const int* __restrict__ ei,
                       const float* __restrict__ prelu_w,
                       const float* __restrict__ mlpW,
                       const float* __restrict__ mlpb, int E) {
    const int e    = (blockIdx.x * blockDim.x + threadIdx.x) >> 5;
    const int lane = threadIdx.x & 31;
    if (e >= E) return;

    const float4 w  = reinterpret_cast<const float4*>(mlpW)[lane];
    const float  pw = prelu_w[0];
    const float  mb = mlpb[0];

    const int src = ei[e];
    const int dst = ei[E + e];

    const float4 a = reinterpret_cast<const float4*>(g_Pj)[(size_t)src * 32 + lane];
    const float4 b = reinterpret_cast<const float4*>(g_Pi)[(size_t)dst * 32 + lane];

    float h, s;
    h = a.x + b.x; h = (h >= 0.f) ? h : pw * h; s  = h * w.x;
    h = a.y + b.y; h = (h >= 0.f) ? h : pw * h; s += h * w.y;
    h = a.z + b.z; h = (h >= 0.f) ? h : pw * h; s += h * w.z;
    h = a.w + b.w; h = (h >= 0.f) ? h : pw * h; s += h * w.w;

#pragma unroll
    for (int o = 16; o > 0; o >>= 1)
        s += __shfl_xor_sync(0xffffffffu, s, o);

    if (lane == 0) g_alpha[e] = s + mb;
}

__global__ __launch_bounds__(256)
void segmax_kernel(const int* __restrict__ seg, int E) {
    int i    = blockIdx.x * blockDim.x + threadIdx.x;
    int lane = threadIdx.x & 31;
    float a = -3.4e38f;
    int   s = -1;
    if (i < E) { a = g_alpha[i]; s = seg[i]; }
#pragma unroll
    for (int o = 1; o < 32; o <<= 1) {
        float av = __shfl_down_sync(0xffffffffu, a, o);
        int   sv = __shfl_down_sync(0xffffffffu, s, o);
        if (lane + o < 32 && sv == s) a = fmaxf(a, av);
    }
    int sp = __shfl_up_sync(0xffffffffu, s, 1);
    bool head = (lane == 0) || (sp != s);
    if (i < E && head) atomicMax(&g_segmax[s], fenc(a));
}

__global__ __launch_bounds__(256)
void expsum_kernel(const int* __restrict__ seg, float* __restrict__ out, int E) {
    int i    = blockIdx.x * blockDim.x + threadIdx.x;
    int lane = threadIdx.x & 31;
    float e = 0.0f;
    int   s = -1;
    if (i < E) {
        s = seg[i];
        float m = fdec(g_segmax[s]);
        e = __expf(g_alpha[i] - m);
        out[i] = e;
    }
    float sum = e;
#pragma unroll
    for (int o = 1; o < 32; o <<= 1) {
        float av = __shfl_down_sync(0xffffffffu, sum, o);
        int   sv = __shfl_down_sync(0xffffffffu, s, o);
        if (lane + o < 32 && sv == s) sum += av;
    }
    int sp = __shfl_up_sync(0xffffffffu, s, 1);
    bool head = (lane == 0) || (sp != s);
    if (i < E && head) atomicAdd(&g_segsum[s], sum);
}

__global__ __launch_bounds__(256)
void norm_kernel(const int* __restrict__ seg, float* __restrict__ out, int E) {
    int i = blockIdx.x * blockDim.x + threadIdx.x;
    if (i < E) out[i] = out[i] / (g_segsum[seg[i]] + 1e-16f);
}

// ---------------------------------------------------------------------------
extern "C" void kernel_launch(void* const* d_in, const int* in_sizes, int n_in,
                              void* d_out, int out_size) {
    const float* x_j   = (const float*)d_in[0];
    const float* x_i   = (const float*)d_in[1];
    const int*   ei    = (const int*)  d_in[2];
    const int*   seg   = (const int*)  d_in[3];
    const float* w_j   = (const float*)d_in[4];
    const float* w_i   = (const float*)d_in[5];
    const float* bias  = (const float*)d_in[6];
    const float* prelu = (const float*)d_in[7];
    const float* mlpW  = (const float*)d_in[8];
    const float* mlpb  = (const float*)d_in[9];

    int nnodes = in_sizes[0] / NF;
    int E      = in_sizes[3];
    float* out = (float*)d_out;

    // raise smem limit (idempotent; no allocation, capture-safe)
    cudaFuncSetAttribute(proj_tc_kernel,
                         cudaFuncAttributeMaxDynamicSharedMemorySize, SMEM_TC);

    init_kernel<<<(NSEG + 255) / 256, 256>>>();

    int gblocks = (nnodes + 127) / 128;
    proj_tc_kernel<<<gblocks, 256, SMEM_TC>>>(x_j, w_j, bias, nnodes, 0);
    proj_tc_kernel<<<gblocks, 256, SMEM_TC>>>(x_i, w_i, bias, nnodes, 1);

    long long nthreads = (long long)E * 32;
    edge_alpha_kernel<<<(unsigned)((nthreads + 255) / 256), 256>>>(
        ei, prelu, mlpW, mlpb, E);

    int eb = (E + 255) / 256;
    segmax_kernel<<<eb, 256>>>(seg, E);
    expsum_kernel<<<eb, 256>>>(seg, out, E);
    norm_kernel  <<<eb, 256>>>(seg, out, E);
}

// round 12
// speedup vs baseline: 2.5228x; 1.2462x over previous
#include <cuda_runtime.h>
#include <cuda_bf16.h>
#include <cstdint>

#define NF   128
#define NSEG 4096
#define MAXN 100000
#define MAXE 1000000

// ---- scratch (device globals: no runtime allocation allowed) ----
__device__ float    g_Pj[MAXN * NF];
__device__ float    g_Pi[MAXN * NF];    // holds Pi + bias (bias folded in epilogue)
__device__ float    g_alpha[MAXE];
__device__ unsigned g_segmax[NSEG];
__device__ float    g_segsum[NSEG];

// monotone float<->uint encoding so atomicMax works on signed floats
__device__ __forceinline__ unsigned fenc(float f) {
    unsigned b = __float_as_uint(f);
    return (b & 0x80000000u) ? ~b : (b | 0x80000000u);
}
__device__ __forceinline__ float fdec(unsigned u) {
    return __uint_as_float((u & 0x80000000u) ? (u & 0x7FFFFFFFu) : ~u);
}

__global__ void init_kernel() {
    int i = blockIdx.x * blockDim.x + threadIdx.x;
    if (i < NSEG) { g_segmax[i] = 0u; g_segsum[i] = 0.0f; }
}

// ---------------------------------------------------------------------------
// mma.sync helpers (baseline PTX — compiles under plain compute_103)
// ---------------------------------------------------------------------------
__device__ __forceinline__ uint32_t smem_u32(const void* p) {
    uint32_t a;
    asm("{ .reg .u64 t; cvta.to.shared.u64 t, %1; cvt.u32.u64 %0, t; }"
        : "=r"(a) : "l"(p));
    return a;
}
__device__ __forceinline__ void ldm_x4(uint32_t* r, uint32_t addr) {
    asm volatile("ldmatrix.sync.aligned.m8n8.x4.shared.b16 {%0,%1,%2,%3}, [%4];"
                 : "=r"(r[0]), "=r"(r[1]), "=r"(r[2]), "=r"(r[3]) : "r"(addr));
}
__device__ __forceinline__ void ldm_x2t(uint32_t* r, uint32_t addr) {
    asm volatile("ldmatrix.sync.aligned.m8n8.x2.trans.shared.b16 {%0,%1}, [%2];"
                 : "=r"(r[0]), "=r"(r[1]) : "r"(addr));
}
__device__ __forceinline__ void mma16816(float* c, const uint32_t* a, const uint32_t* b) {
    asm volatile(
        "mma.sync.aligned.m16n8k16.row.col.f32.bf16.bf16.f32 "
        "{%0,%1,%2,%3}, {%4,%5,%6,%7}, {%8,%9}, {%0,%1,%2,%3};"
        : "+f"(c[0]), "+f"(c[1]), "+f"(c[2]), "+f"(c[3])
        : "r"(a[0]), "r"(a[1]), "r"(a[2]), "r"(a[3]), "r"(b[0]), "r"(b[1]));
}
__device__ __forceinline__ void split2(float x, float y, uint32_t& hi, uint32_t& lo) {
    __nv_bfloat16 hx = __float2bfloat16(x), hy = __float2bfloat16(y);
    __nv_bfloat16 lx = __float2bfloat16(x - __bfloat162float(hx));
    __nv_bfloat16 ly = __float2bfloat16(y - __bfloat162float(hy));
    hi = (uint32_t)__bfloat16_as_ushort(hx) | ((uint32_t)__bfloat16_as_ushort(hy) << 16);
    lo = (uint32_t)__bfloat16_as_ushort(lx) | ((uint32_t)__bfloat16_as_ushort(ly) << 16);
}

// ---------------------------------------------------------------------------
// Tensor-core projection (unchanged from R10 — measured ~58 us/launch):
// P[tile 128x128] = X_tile @ W (+bias if which==1)
// bf16 split-GEMM: D = Ahi*Whi + Alo*Whi + Ahi*Wlo, fp32 accumulators.
// ---------------------------------------------------------------------------
#define TCP 136
#define PLANE (128 * TCP * 2)
#define SM_WH 0
#define SM_WL (PLANE)
#define SM_AH (2 * PLANE)
#define SM_AL (3 * PLANE)
#define SMEM_TC (4 * PLANE)

__global__ __launch_bounds__(256)
void proj_tc_kernel(const float* __restrict__ X, const float* __restrict__ W,
                    const float* __restrict__ bias, int nrows, int which) {
    extern __shared__ char smem[];
    float* __restrict__ P = which ? g_Pi : g_Pj;
    const int tid = threadIdx.x, wid = tid >> 5, lane = tid & 31;
    const int rowBase = blockIdx.x * 128;

#pragma unroll
    for (int it = 0; it < 16; ++it) {
        int f = it * 256 + tid;
        int k = f >> 5, c4 = (f & 31) * 4;
        float4 v = *reinterpret_cast<const float4*>(W + k * NF + c4);
        uint2 h, l;
        split2(v.x, v.y, h.x, l.x);
        split2(v.z, v.w, h.y, l.y);
        uint32_t off = (uint32_t)(k * TCP + c4) * 2;
        *reinterpret_cast<uint2*>(smem + SM_WH + off) = h;
        *reinterpret_cast<uint2*>(smem + SM_WL + off) = l;
    }
#pragma unroll
    for (int it = 0; it < 16; ++it) {
        int f = it * 256 + tid;
        int r = f >> 5, c4 = (f & 31) * 4;
        int gr = rowBase + r;
        float4 v = make_float4(0.f, 0.f, 0.f, 0.f);
        if (gr < nrows) v = *reinterpret_cast<const float4*>(X + gr * NF + c4);
        uint2 h, l;
        split2(v.x, v.y, h.x, l.x);
        split2(v.z, v.w, h.y, l.y);
        uint32_t off = (uint32_t)(r * TCP + c4) * 2;
        *reinterpret_cast<uint2*>(smem + SM_AH + off) = h;
        *reinterpret_cast<uint2*>(smem + SM_AL + off) = l;
    }
    __syncthreads();

    const int wr = wid >> 2;
    const int wc = wid & 3;
    const uint32_t sb = smem_u32(smem);

    float acc[4][4][4];
#pragma unroll
    for (int mt = 0; mt < 4; ++mt)
#pragma unroll
        for (int nt = 0; nt < 4; ++nt)
#pragma unroll
            for (int c = 0; c < 4; ++c) acc[mt][nt][c] = 0.0f;

    const int aRow = wr * 64 + (lane & 15);
    const int aCol = (lane >> 4) << 3;
    const int bCol = wc * 32;
    const int bRowL = (lane & 15);

#pragma unroll
    for (int split = 0; split < 3; ++split) {
        const uint32_t aBase = sb + ((split == 1) ? SM_AL : SM_AH);
        const uint32_t bBase = sb + ((split == 2) ? SM_WL : SM_WH);
#pragma unroll
        for (int kk = 0; kk < 128; kk += 16) {
            uint32_t a[4][4], b[4][2];
#pragma unroll
            for (int mt = 0; mt < 4; ++mt)
                ldm_x4(a[mt], aBase + (uint32_t)((aRow + mt * 16) * TCP + aCol + kk) * 2);
#pragma unroll
            for (int nt = 0; nt < 4; ++nt)
                ldm_x2t(b[nt], bBase + (uint32_t)((bRowL + kk) * TCP + bCol + nt * 8) * 2);
#pragma unroll
            for (int mt = 0; mt < 4; ++mt)
#pragma unroll
                for (int nt = 0; nt < 4; ++nt)
                    mma16816(acc[mt][nt], a[mt], b[nt]);
        }
    }
    __syncthreads();

    float* ds = reinterpret_cast<float*>(smem);
    const int cr = lane >> 2;
    const int cc = (lane & 3) * 2;
#pragma unroll
    for (int mt = 0; mt < 4; ++mt)
#pragma unroll
        for (int nt = 0; nt < 4; ++nt) {
            int r0 = wr * 64 + mt * 16 + cr;
            int c0 = wc * 32 + nt * 8 + cc;
            ds[r0 * 129 + c0]           = acc[mt][nt][0];
            ds[r0 * 129 + c0 + 1]       = acc[mt][nt][1];
            ds[(r0 + 8) * 129 + c0]     = acc[mt][nt][2];
            ds[(r0 + 8) * 129 + c0 + 1] = acc[mt][nt][3];
        }
    __syncthreads();
#pragma unroll
    for (int it = 0; it < 16; ++it) {
        int f = it * 256 + tid;
        int r = f >> 5, c4 = (f & 31) * 4;
        int gr = rowBase + r;
        if (gr < nrows) {
            float4 o;
            o.x = ds[r * 129 + c4 + 0];
            o.y = ds[r * 129 + c4 + 1];
            o.z = ds[r * 129 + c4 + 2];
            o.w = ds[r * 129 + c4 + 3];
            if (which) {
                float4 bv = *reinterpret_cast<const float4*>(bias + c4);
                o.x += bv.x; o.y += bv.y; o.z += bv.z; o.w += bv.w;
            }
            *reinterpret_cast<float4*>(P + gr * NF + c4) = o;
        }
    }
}

// ---------------------------------------------------------------------------
// alpha[e] = PReLU(Pj[src] + Pi'[dst]) . mlpW + mlpb   (bias already in Pi')
// PERSISTENT grid-stride version: per-iteration body is byte-identical to the
// proven R2 layout (one warp = one edge, 2 coalesced gathers, broadcast ei,
// lane-0 store), but mlpW/prelu/mlpb are loaded ONCE per warp lifetime
// instead of once per edge (-4..6 L1 wavefronts per edge).
// ---------------------------------------------------------------------------
#define EDGE_BLOCKS 1184   // 8 per SM x 148
__global__ __launch_bounds__(256)
void edge_alpha_kernel(const int* __restrict__ ei,
                       const float* __restrict__ prelu_w,
                       const float* __restrict__ mlpW,
                       const float* __restrict__ mlpb, int E) {
    const int lane   = threadIdx.x & 31;
    const int warpId = (blockIdx.x * blockDim.x + threadIdx.x) >> 5;
    const int nwarps = (EDGE_BLOCKS * 256) >> 5;

    const float4 w  = reinterpret_cast<const float4*>(mlpW)[lane];
    const float  pw = prelu_w[0];
    const float  mb = mlpb[0];

    for (int e = warpId; e < E; e += nwarps) {
        const int src = ei[e];          // warp-uniform -> broadcast wavefront
        const int dst = ei[E + e];

        const float4 a = reinterpret_cast<const float4*>(g_Pj)[(size_t)src * 32 + lane];
        const float4 b = reinterpret_cast<const float4*>(g_Pi)[(size_t)dst * 32 + lane];

        float h, s;
        h = a.x + b.x; h = (h >= 0.f) ? h : pw * h; s  = h * w.x;
        h = a.y + b.y; h = (h >= 0.f) ? h : pw * h; s += h * w.y;
        h = a.z + b.z; h = (h >= 0.f) ? h : pw * h; s += h * w.z;
        h = a.w + b.w; h = (h >= 0.f) ? h : pw * h; s += h * w.w;

#pragma unroll
        for (int o = 16; o > 0; o >>= 1)
            s += __shfl_xor_sync(0xffffffffu, s, o);

        if (lane == 0) g_alpha[e] = s + mb;
    }
}

__global__ __launch_bounds__(256)
void segmax_kernel(const int* __restrict__ seg, int E) {
    int i    = blockIdx.x * blockDim.x + threadIdx.x;
    int lane = threadIdx.x & 31;
    float a = -3.4e38f;
    int   s = -1;
    if (i < E) { a = g_alpha[i]; s = seg[i]; }
#pragma unroll
    for (int o = 1; o < 32; o <<= 1) {
        float av = __shfl_down_sync(0xffffffffu, a, o);
        int   sv = __shfl_down_sync(0xffffffffu, s, o);
        if (lane + o < 32 && sv == s) a = fmaxf(a, av);
    }
    int sp = __shfl_up_sync(0xffffffffu, s, 1);
    bool head = (lane == 0) || (sp != s);
    if (i < E && head) atomicMax(&g_segmax[s], fenc(a));
}

__global__ __launch_bounds__(256)
void expsum_kernel(const int* __restrict__ seg, float* __restrict__ out, int E) {
    int i    = blockIdx.x * blockDim.x + threadIdx.x;
    int lane = threadIdx.x & 31;
    float e = 0.0f;
    int   s = -1;
    if (i < E) {
        s = seg[i];
        float m = fdec(g_segmax[s]);
        e = __expf(g_alpha[i] - m);
        out[i] = e;
    }
    float sum = e;
#pragma unroll
    for (int o = 1; o < 32; o <<= 1) {
        float av = __shfl_down_sync(0xffffffffu, sum, o);
        int   sv = __shfl_down_sync(0xffffffffu, s, o);
        if (lane + o < 32 && sv == s) sum += av;
    }
    int sp = __shfl_up_sync(0xffffffffu, s, 1);
    bool head = (lane == 0) || (sp != s);
    if (i < E && head) atomicAdd(&g_segsum[s], sum);
}

__global__ __launch_bounds__(256)
void norm_kernel(const int* __restrict__ seg, float* __restrict__ out, int E) {
    int i = blockIdx.x * blockDim.x + threadIdx.x;
    if (i < E) out[i] = out[i] / (g_segsum[seg[i]] + 1e-16f);
}

// ---------------------------------------------------------------------------
extern "C" void kernel_launch(void* const* d_in, const int* in_sizes, int n_in,
                              void* d_out, int out_size) {
    const float* x_j   = (const float*)d_in[0];
    const float* x_i   = (const float*)d_in[1];
    const int*   ei    = (const int*)  d_in[2];
    const int*   seg   = (const int*)  d_in[3];
    const float* w_j   = (const float*)d_in[4];
    const float* w_i   = (const float*)d_in[5];
    const float* bias  = (const float*)d_in[6];
    const float* prelu = (const float*)d_in[7];
    const float* mlpW  = (const float*)d_in[8];
    const float* mlpb  = (const float*)d_in[9];

    int nnodes = in_sizes[0] / NF;
    int E      = in_sizes[3];
    float* out = (float*)d_out;

    cudaFuncSetAttribute(proj_tc_kernel,
                         cudaFuncAttributeMaxDynamicSharedMemorySize, SMEM_TC);

    init_kernel<<<(NSEG + 255) / 256, 256>>>();

    int gblocks = (nnodes + 127) / 128;
    proj_tc_kernel<<<gblocks, 256, SMEM_TC>>>(x_j, w_j, bias, nnodes, 0);
    proj_tc_kernel<<<gblocks, 256, SMEM_TC>>>(x_i, w_i, bias, nnodes, 1);

    edge_alpha_kernel<<<EDGE_BLOCKS, 256>>>(ei, prelu, mlpW, mlpb, E);

    int eb = (E + 255) / 256;
    segmax_kernel<<<eb, 256>>>(seg, E);
    expsum_kernel<<<eb, 256>>>(seg, out, E);
    norm_kernel  <<<eb, 256>>>(seg, out, E);
}

// round 13
// speedup vs baseline: 2.6344x; 1.0442x over previous
#include <cuda_runtime.h>
#include <cuda_bf16.h>
#include <cstdint>

#define NF   128
#define NSEG 4096
#define MAXN 100000
#define MAXE 1000000

// ---- scratch (device globals: no runtime allocation allowed) ----
__device__ float    g_Pj[MAXN * NF];
__device__ float    g_Pi[MAXN * NF];    // holds Pi + bias (bias folded in epilogue)
__device__ float    g_alpha[MAXE];
__device__ unsigned g_segmax[NSEG];
__device__ float    g_segsum[NSEG];

// monotone float<->uint encoding so atomicMax works on signed floats
__device__ __forceinline__ unsigned fenc(float f) {
    unsigned b = __float_as_uint(f);
    return (b & 0x80000000u) ? ~b : (b | 0x80000000u);
}
__device__ __forceinline__ float fdec(unsigned u) {
    return __uint_as_float((u & 0x80000000u) ? (u & 0x7FFFFFFFu) : ~u);
}

__global__ void init_kernel() {
    int i = blockIdx.x * blockDim.x + threadIdx.x;
    if (i < NSEG) { g_segmax[i] = 0u; g_segsum[i] = 0.0f; }
}

// ---------------------------------------------------------------------------
// mma.sync helpers (baseline PTX — compiles under plain compute_103)
// ---------------------------------------------------------------------------
__device__ __forceinline__ uint32_t smem_u32(const void* p) {
    uint32_t a;
    asm("{ .reg .u64 t; cvta.to.shared.u64 t, %1; cvt.u32.u64 %0, t; }"
        : "=r"(a) : "l"(p));
    return a;
}
__device__ __forceinline__ void ldm_x4(uint32_t* r, uint32_t addr) {
    asm volatile("ldmatrix.sync.aligned.m8n8.x4.shared.b16 {%0,%1,%2,%3}, [%4];"
                 : "=r"(r[0]), "=r"(r[1]), "=r"(r[2]), "=r"(r[3]) : "r"(addr));
}
__device__ __forceinline__ void ldm_x2t(uint32_t* r, uint32_t addr) {
    asm volatile("ldmatrix.sync.aligned.m8n8.x2.trans.shared.b16 {%0,%1}, [%2];"
                 : "=r"(r[0]), "=r"(r[1]) : "r"(addr));
}
__device__ __forceinline__ void mma16816(float* c, const uint32_t* a, const uint32_t* b) {
    asm volatile(
        "mma.sync.aligned.m16n8k16.row.col.f32.bf16.bf16.f32 "
        "{%0,%1,%2,%3}, {%4,%5,%6,%7}, {%8,%9}, {%0,%1,%2,%3};"
        : "+f"(c[0]), "+f"(c[1]), "+f"(c[2]), "+f"(c[3])
        : "r"(a[0]), "r"(a[1]), "r"(a[2]), "r"(a[3]), "r"(b[0]), "r"(b[1]));
}
__device__ __forceinline__ void split2(float x, float y, uint32_t& hi, uint32_t& lo) {
    __nv_bfloat16 hx = __float2bfloat16(x), hy = __float2bfloat16(y);
    __nv_bfloat16 lx = __float2bfloat16(x - __bfloat162float(hx));
    __nv_bfloat16 ly = __float2bfloat16(y - __bfloat162float(hy));
    hi = (uint32_t)__bfloat16_as_ushort(hx) | ((uint32_t)__bfloat16_as_ushort(hy) << 16);
    lo = (uint32_t)__bfloat16_as_ushort(lx) | ((uint32_t)__bfloat16_as_ushort(ly) << 16);
}

// ---------------------------------------------------------------------------
// Tensor-core projection (unchanged from R10/R11 — measured ~58 us/launch):
// P[tile 128x128] = X_tile @ W (+bias if which==1)
// bf16 split-GEMM: D = Ahi*Whi + Alo*Whi + Ahi*Wlo, fp32 accumulators.
// ---------------------------------------------------------------------------
#define TCP 136
#define PLANE (128 * TCP * 2)
#define SM_WH 0
#define SM_WL (PLANE)
#define SM_AH (2 * PLANE)
#define SM_AL (3 * PLANE)
#define SMEM_TC (4 * PLANE)

__global__ __launch_bounds__(256)
void proj_tc_kernel(const float* __restrict__ X, const float* __restrict__ W,
                    const float* __restrict__ bias, int nrows, int which) {
    extern __shared__ char smem[];
    float* __restrict__ P = which ? g_Pi : g_Pj;
    const int tid = threadIdx.x, wid = tid >> 5, lane = tid & 31;
    const int rowBase = blockIdx.x * 128;

#pragma unroll
    for (int it = 0; it < 16; ++it) {
        int f = it * 256 + tid;
        int k = f >> 5, c4 = (f & 31) * 4;
        float4 v = *reinterpret_cast<const float4*>(W + k * NF + c4);
        uint2 h, l;
        split2(v.x, v.y, h.x, l.x);
        split2(v.z, v.w, h.y, l.y);
        uint32_t off = (uint32_t)(k * TCP + c4) * 2;
        *reinterpret_cast<uint2*>(smem + SM_WH + off) = h;
        *reinterpret_cast<uint2*>(smem + SM_WL + off) = l;
    }
#pragma unroll
    for (int it = 0; it < 16; ++it) {
        int f = it * 256 + tid;
        int r = f >> 5, c4 = (f & 31) * 4;
        int gr = rowBase + r;
        float4 v = make_float4(0.f, 0.f, 0.f, 0.f);
        if (gr < nrows) v = *reinterpret_cast<const float4*>(X + gr * NF + c4);
        uint2 h, l;
        split2(v.x, v.y, h.x, l.x);
        split2(v.z, v.w, h.y, l.y);
        uint32_t off = (uint32_t)(r * TCP + c4) * 2;
        *reinterpret_cast<uint2*>(smem + SM_AH + off) = h;
        *reinterpret_cast<uint2*>(smem + SM_AL + off) = l;
    }
    __syncthreads();

    const int wr = wid >> 2;
    const int wc = wid & 3;
    const uint32_t sb = smem_u32(smem);

    float acc[4][4][4];
#pragma unroll
    for (int mt = 0; mt < 4; ++mt)
#pragma unroll
        for (int nt = 0; nt < 4; ++nt)
#pragma unroll
            for (int c = 0; c < 4; ++c) acc[mt][nt][c] = 0.0f;

    const int aRow = wr * 64 + (lane & 15);
    const int aCol = (lane >> 4) << 3;
    const int bCol = wc * 32;
    const int bRowL = (lane & 15);

#pragma unroll
    for (int split = 0; split < 3; ++split) {
        const uint32_t aBase = sb + ((split == 1) ? SM_AL : SM_AH);
        const uint32_t bBase = sb + ((split == 2) ? SM_WL : SM_WH);
#pragma unroll
        for (int kk = 0; kk < 128; kk += 16) {
            uint32_t a[4][4], b[4][2];
#pragma unroll
            for (int mt = 0; mt < 4; ++mt)
                ldm_x4(a[mt], aBase + (uint32_t)((aRow + mt * 16) * TCP + aCol + kk) * 2);
#pragma unroll
            for (int nt = 0; nt < 4; ++nt)
                ldm_x2t(b[nt], bBase + (uint32_t)((bRowL + kk) * TCP + bCol + nt * 8) * 2);
#pragma unroll
            for (int mt = 0; mt < 4; ++mt)
#pragma unroll
                for (int nt = 0; nt < 4; ++nt)
                    mma16816(acc[mt][nt], a[mt], b[nt]);
        }
    }
    __syncthreads();

    float* ds = reinterpret_cast<float*>(smem);
    const int cr = lane >> 2;
    const int cc = (lane & 3) * 2;
#pragma unroll
    for (int mt = 0; mt < 4; ++mt)
#pragma unroll
        for (int nt = 0; nt < 4; ++nt) {
            int r0 = wr * 64 + mt * 16 + cr;
            int c0 = wc * 32 + nt * 8 + cc;
            ds[r0 * 129 + c0]           = acc[mt][nt][0];
            ds[r0 * 129 + c0 + 1]       = acc[mt][nt][1];
            ds[(r0 + 8) * 129 + c0]     = acc[mt][nt][2];
            ds[(r0 + 8) * 129 + c0 + 1] = acc[mt][nt][3];
        }
    __syncthreads();
#pragma unroll
    for (int it = 0; it < 16; ++it) {
        int f = it * 256 + tid;
        int r = f >> 5, c4 = (f & 31) * 4;
        int gr = rowBase + r;
        if (gr < nrows) {
            float4 o;
            o.x = ds[r * 129 + c4 + 0];
            o.y = ds[r * 129 + c4 + 1];
            o.z = ds[r * 129 + c4 + 2];
            o.w = ds[r * 129 + c4 + 3];
            if (which) {
                float4 bv = *reinterpret_cast<const float4*>(bias + c4);
                o.x += bv.x; o.y += bv.y; o.z += bv.z; o.w += bv.w;
            }
            *reinterpret_cast<float4*>(P + gr * NF + c4) = o;
        }
    }
}

// ---------------------------------------------------------------------------
// alpha[e] = PReLU(Pj[src] + Pi'[dst]) . mlpW + mlpb   (bias already in Pi')
// Persistent CHUNKED warps: each warp owns ~106 CONSECUTIVE edges.
//  - per-edge body identical to the proven layout (coalesced float4 gathers,
//    warp-uniform ei loads, lane-0 store)
//  - 2 edges per iteration -> 4 gathers in flight (MLP=4, hides DRAM misses)
//  - fused segmented max: sorted seg ids + contiguous chunk => lane 0 keeps a
//    running (seg,max), flushing an atomicMax only at run boundaries
//    (~3 flushes per chunk, ~30K atomics total) -> segmax pass deleted.
// ---------------------------------------------------------------------------
#define EDGE_BLOCKS 1184   // 8 per SM x 148
__global__ __launch_bounds__(256)
void edge_alpha_kernel(const int* __restrict__ ei,
                       const int* __restrict__ seg,
                       const float* __restrict__ prelu_w,
                       const float* __restrict__ mlpW,
                       const float* __restrict__ mlpb, int E) {
    const int lane   = threadIdx.x & 31;
    const int warpId = (blockIdx.x * blockDim.x + threadIdx.x) >> 5;
    const int nwarps = (EDGE_BLOCKS * 256) >> 5;

    const int chunk = (E + nwarps - 1) / nwarps;
    const int e0 = warpId * chunk;
    const int e1 = (e0 + chunk < E) ? (e0 + chunk) : E;
    if (e0 >= E) return;

    const float4 w  = reinterpret_cast<const float4*>(mlpW)[lane];
    const float  pw = prelu_w[0];
    const float  mb = mlpb[0];

    float runm = 0.0f;   // running segment max (lane 0 only)
    int   runs = -1;

    for (int e = e0; e < e1; e += 2) {
        const bool two = (e + 1 < e1);
        const int src0 = ei[e];
        const int dst0 = ei[E + e];
        const int src1 = two ? ei[e + 1]     : src0;
        const int dst1 = two ? ei[E + e + 1] : dst0;

        // 4 independent coalesced gathers in flight
        const float4 a0 = reinterpret_cast<const float4*>(g_Pj)[(size_t)src0 * 32 + lane];
        const float4 b0 = reinterpret_cast<const float4*>(g_Pi)[(size_t)dst0 * 32 + lane];
        const float4 a1 = reinterpret_cast<const float4*>(g_Pj)[(size_t)src1 * 32 + lane];
        const float4 b1 = reinterpret_cast<const float4*>(g_Pi)[(size_t)dst1 * 32 + lane];

        float h, s0, s1;
        h = a0.x + b0.x; h = (h >= 0.f) ? h : pw * h; s0  = h * w.x;
        h = a0.y + b0.y; h = (h >= 0.f) ? h : pw * h; s0 += h * w.y;
        h = a0.z + b0.z; h = (h >= 0.f) ? h : pw * h; s0 += h * w.z;
        h = a0.w + b0.w; h = (h >= 0.f) ? h : pw * h; s0 += h * w.w;
        h = a1.x + b1.x; h = (h >= 0.f) ? h : pw * h; s1  = h * w.x;
        h = a1.y + b1.y; h = (h >= 0.f) ? h : pw * h; s1 += h * w.y;
        h = a1.z + b1.z; h = (h >= 0.f) ? h : pw * h; s1 += h * w.z;
        h = a1.w + b1.w; h = (h >= 0.f) ? h : pw * h; s1 += h * w.w;

#pragma unroll
        for (int o = 16; o > 0; o >>= 1) {
            s0 += __shfl_xor_sync(0xffffffffu, s0, o);
            s1 += __shfl_xor_sync(0xffffffffu, s1, o);
        }

        if (lane == 0) {
            const float al0 = s0 + mb;
            g_alpha[e] = al0;
            const int sg0 = seg[e];
            if (sg0 == runs) runm = fmaxf(runm, al0);
            else {
                if (runs >= 0) atomicMax(&g_segmax[runs], fenc(runm));
                runs = sg0; runm = al0;
            }
            if (two) {
                const float al1 = s1 + mb;
                g_alpha[e + 1] = al1;
                const int sg1 = seg[e + 1];
                if (sg1 == runs) runm = fmaxf(runm, al1);
                else {
                    atomicMax(&g_segmax[runs], fenc(runm));
                    runs = sg1; runm = al1;
                }
            }
        }
    }
    if (lane == 0 && runs >= 0) atomicMax(&g_segmax[runs], fenc(runm));
}

// e = exp(alpha - segmax); store to out; warp-segmented suffix-sum + atomicAdd
__global__ __launch_bounds__(256)
void expsum_kernel(const int* __restrict__ seg, float* __restrict__ out, int E) {
    int i    = blockIdx.x * blockDim.x + threadIdx.x;
    int lane = threadIdx.x & 31;
    float e = 0.0f;
    int   s = -1;
    if (i < E) {
        s = seg[i];
        float m = fdec(g_segmax[s]);
        e = __expf(g_alpha[i] - m);
        out[i] = e;
    }
    float sum = e;
#pragma unroll
    for (int o = 1; o < 32; o <<= 1) {
        float av = __shfl_down_sync(0xffffffffu, sum, o);
        int   sv = __shfl_down_sync(0xffffffffu, s, o);
        if (lane + o < 32 && sv == s) sum += av;
    }
    int sp = __shfl_up_sync(0xffffffffu, s, 1);
    bool head = (lane == 0) || (sp != s);
    if (i < E && head) atomicAdd(&g_segsum[s], sum);
}

__global__ __launch_bounds__(256)
void norm_kernel(const int* __restrict__ seg, float* __restrict__ out, int E) {
    int i = blockIdx.x * blockDim.x + threadIdx.x;
    if (i < E) out[i] = out[i] / (g_segsum[seg[i]] + 1e-16f);
}

// ---------------------------------------------------------------------------
extern "C" void kernel_launch(void* const* d_in, const int* in_sizes, int n_in,
                              void* d_out, int out_size) {
    const float* x_j   = (const float*)d_in[0];
    const float* x_i   = (const float*)d_in[1];
    const int*   ei    = (const int*)  d_in[2];
    const int*   seg   = (const int*)  d_in[3];
    const float* w_j   = (const float*)d_in[4];
    const float* w_i   = (const float*)d_in[5];
    const float* bias  = (const float*)d_in[6];
    const float* prelu = (const float*)d_in[7];
    const float* mlpW  = (const float*)d_in[8];
    const float* mlpb  = (const float*)d_in[9];

    int nnodes = in_sizes[0] / NF;
    int E      = in_sizes[3];
    float* out = (float*)d_out;

    cudaFuncSetAttribute(proj_tc_kernel,
                         cudaFuncAttributeMaxDynamicSharedMemorySize, SMEM_TC);

    init_kernel<<<(NSEG + 255) / 256, 256>>>();

    int gblocks = (nnodes + 127) / 128;
    proj_tc_kernel<<<gblocks, 256, SMEM_TC>>>(x_j, w_j, bias, nnodes, 0);
    proj_tc_kernel<<<gblocks, 256, SMEM_TC>>>(x_i, w_i, bias, nnodes, 1);

    edge_alpha_kernel<<<EDGE_BLOCKS, 256>>>(ei, seg, prelu, mlpW, mlpb, E);

    int eb = (E + 255) / 256;
    expsum_kernel<<<eb, 256>>>(seg, out, E);
    norm_kernel  <<<eb, 256>>>(seg, out, E);
}